// round 13
// baseline (speedup 1.0000x reference)
#include <cuda_runtime.h>
#include <math.h>
#include <stdint.h>

// ---------------------------------------------------------------- constants
#define BB 64
#define NN 197
#define CC 768
#define HH 12
#define HD 64
#define C3 2304
#define C4 3072
#define MR (BB*NN)        /* 12608 rows */
#define BH (BB*HH)        /* 768 (b,h) pairs */
#define LN_EPS 1e-5f

// ---------------------------------------------------------------- scratch
__device__ __align__(16) float g_xn  [(size_t)MR * CC];
__device__ __align__(16) float g_qkv [(size_t)MR * C3];
__device__ __align__(16) float g_attn[(size_t)BH * NN * NN];
__device__ __align__(16) float g_xo  [(size_t)MR * CC];
__device__ __align__(16) float g_x2  [(size_t)MR * CC];
__device__ __align__(16) float g_ln2 [(size_t)MR * CC];
__device__ __align__(16) float g_fc1 [(size_t)MR * C4];
__device__ int   g_rowmap[MR];
__device__ float g_pol   [MR];

// ---------------------------------------------------------------- helpers
__device__ __forceinline__ uint32_t f2tf32(float x) {
    uint32_t u;
    asm("cvt.rna.tf32.f32 %0, %1;" : "=r"(u) : "f"(x));
    return u;
}
__device__ __forceinline__ void cp_async16(uint32_t saddr, const void* gptr, uint32_t srcsz) {
    asm volatile("cp.async.cg.shared.global [%0], [%1], 16, %2;\n"
                 :: "r"(saddr), "l"(gptr), "r"(srcsz));
}
__device__ __forceinline__ void cp_commit() {
    asm volatile("cp.async.commit_group;\n");
}
template <int N>
__device__ __forceinline__ void cp_wait() {
    asm volatile("cp.async.wait_group %0;\n" :: "n"(N));
}

// ---------------------------------------------------------------- LayerNorm
__global__ void ln_kernel(const float* __restrict__ Xin,
                          const float* __restrict__ gam,
                          const float* __restrict__ bet,
                          int mode)
{
    const float* X = (mode == 0) ? Xin : g_x2;
    float*       Y = (mode == 0) ? g_xn : g_ln2;

    __shared__ float red[40];
    int row = blockIdx.x;
    int t   = threadIdx.x;
    const float* x = X + (size_t)row * CC;

    float v0 = x[t], v1 = x[t + 256], v2 = x[t + 512];

    float s = v0 + v1 + v2;
    #pragma unroll
    for (int o = 16; o > 0; o >>= 1) s += __shfl_xor_sync(0xffffffffu, s, o);
    if ((t & 31) == 0) red[t >> 5] = s;
    __syncthreads();
    if (t < 32) {
        float r = (t < 8) ? red[t] : 0.0f;
        #pragma unroll
        for (int o = 4; o > 0; o >>= 1) r += __shfl_xor_sync(0xffffffffu, r, o);
        if (t == 0) red[32] = r;
    }
    __syncthreads();
    float mean = red[32] * (1.0f / 768.0f);
    __syncthreads();

    float d0 = v0 - mean, d1 = v1 - mean, d2 = v2 - mean;
    s = d0 * d0 + d1 * d1 + d2 * d2;
    #pragma unroll
    for (int o = 16; o > 0; o >>= 1) s += __shfl_xor_sync(0xffffffffu, s, o);
    if ((t & 31) == 0) red[t >> 5] = s;
    __syncthreads();
    if (t < 32) {
        float r = (t < 8) ? red[t] : 0.0f;
        #pragma unroll
        for (int o = 4; o > 0; o >>= 1) r += __shfl_xor_sync(0xffffffffu, r, o);
        if (t == 0) red[33] = r;
    }
    __syncthreads();
    float var  = red[33] * (1.0f / 768.0f);
    float rstd = 1.0f / sqrtf(var + LN_EPS);

    float* y = Y + (size_t)row * CC;
    y[t]       = d0 * rstd * gam[t]       + bet[t];
    y[t + 256] = d1 * rstd * gam[t + 256] + bet[t + 256];
    y[t + 512] = d2 * rstd * gam[t + 512] + bet[t + 512];
}

// ---------------------------------------------------------------- fp32 SGEMM (QKV)
// g_xn @ w_qkv(768x2304) -> g_qkv ; epilogue: * policy[row]
// MUST stay fp32: qkv feeds the discrete sampling path (empirically, 3xTF32's
// ~6e-6 noise flips picks; fp32's ~1.6e-6 does not).
// Register-prefetch + double-buffered smem: one __syncthreads per k-tile.
// Accumulation order over k is IDENTICAL to the R10 passing kernel.
__global__ __launch_bounds__(256)
void sgemm_qkv(const float* __restrict__ Bm, const float* __restrict__ policy)
{
    const int Nn = C3, Kk = CC;
    const int NT = Kk / 16;             // 48 k-tiles

    __shared__ float As[2][16][128];
    __shared__ float Bs[2][16][128];

    int tid  = threadIdx.x;
    int bx   = blockIdx.x;
    int row0 = blockIdx.y * 128;
    int tx   = tid & 15;
    int ty   = tid >> 4;

    int a_r = tid >> 2;             // 0..63
    int a_c = (tid & 3) << 2;       // 0,4,8,12
    int b_r = tid >> 5;             // 0..7
    int b_c = (tid & 31) << 2;      // 0..124

    float4 pa[2], pb[2];

    // prologue: load tile 0
    #pragma unroll
    for (int p = 0; p < 2; p++) {
        int r = row0 + a_r + p * 64;
        pa[p] = (r < MR) ? *(const float4*)(g_xn + (size_t)r * Kk + a_c)
                         : make_float4(0.f, 0.f, 0.f, 0.f);
        int kr = b_r + p * 8;
        pb[p] = *(const float4*)(Bm + (size_t)kr * Nn + bx * 128 + b_c);
    }
    #pragma unroll
    for (int p = 0; p < 2; p++) {
        As[0][a_c + 0][a_r + p * 64] = pa[p].x;
        As[0][a_c + 1][a_r + p * 64] = pa[p].y;
        As[0][a_c + 2][a_r + p * 64] = pa[p].z;
        As[0][a_c + 3][a_r + p * 64] = pa[p].w;
        *(float4*)(&Bs[0][b_r + p * 8][b_c]) = pb[p];
    }
    __syncthreads();

    float acc[8][8];
    #pragma unroll
    for (int i = 0; i < 8; i++)
        #pragma unroll
        for (int j = 0; j < 8; j++) acc[i][j] = 0.0f;

    for (int kt = 0; kt < NT; kt++) {
        int buf = kt & 1;

        // prefetch next tile into registers (hidden under the FFMA block)
        if (kt + 1 < NT) {
            int k0 = (kt + 1) * 16;
            #pragma unroll
            for (int p = 0; p < 2; p++) {
                int r = row0 + a_r + p * 64;
                pa[p] = (r < MR)
                    ? *(const float4*)(g_xn + (size_t)r * Kk + k0 + a_c)
                    : make_float4(0.f, 0.f, 0.f, 0.f);
                int kr = k0 + b_r + p * 8;
                pb[p] = *(const float4*)(Bm + (size_t)kr * Nn + bx * 128 + b_c);
            }
        }

        #pragma unroll
        for (int k = 0; k < 16; k++) {
            float af[8], bf[8];
            *(float4*)(af)     = *(const float4*)(&As[buf][k][ty * 4]);
            *(float4*)(af + 4) = *(const float4*)(&As[buf][k][ty * 4 + 64]);
            *(float4*)(bf)     = *(const float4*)(&Bs[buf][k][tx * 4]);
            *(float4*)(bf + 4) = *(const float4*)(&Bs[buf][k][tx * 4 + 64]);
            #pragma unroll
            for (int i = 0; i < 8; i++)
                #pragma unroll
                for (int j = 0; j < 8; j++)
                    acc[i][j] = fmaf(af[i], bf[j], acc[i][j]);
        }

        if (kt + 1 < NT) {
            int nb = buf ^ 1;
            #pragma unroll
            for (int p = 0; p < 2; p++) {
                As[nb][a_c + 0][a_r + p * 64] = pa[p].x;
                As[nb][a_c + 1][a_r + p * 64] = pa[p].y;
                As[nb][a_c + 2][a_r + p * 64] = pa[p].z;
                As[nb][a_c + 3][a_r + p * 64] = pa[p].w;
                *(float4*)(&Bs[nb][b_r + p * 8][b_c]) = pb[p];
            }
            __syncthreads();
        }
    }

    #pragma unroll
    for (int i = 0; i < 8; i++) {
        int row = row0 + ty * 4 + ((i & 4) ? 64 : 0) + (i & 3);
        if (row >= MR) continue;
        float prow = policy[row];
        #pragma unroll
        for (int j = 0; j < 8; j++) {
            int col = bx * 128 + tx * 4 + ((j & 4) ? 64 : 0) + (j & 3);
            g_qkv[(size_t)row * Nn + col] = acc[i][j] * prow;
        }
    }
}

// ---------------------------------------------------------------- TF32 tensor-core GEMM
// 128x128x32 CTA tile, 8 warps (2x4) of 64x32, mma.m16n8k8 tf32.
// cp.async double-buffered smem; cvt.rna.tf32 at fragment load.
// MODE 1: g_xo  @ Bm(768x768)  -> g_x2  ; epi: xgather + (acc+b)*pol  (aux = x)
// MODE 2: g_ln2 @ Bm(768x3072) -> g_fc1 ; epi: exact GELU(acc+b)
// MODE 3: g_fc1 @ Bm(3072x768) -> Cext  ; epi: (g_x2 + acc + b)*pol
#define ASTRIDE 36
#define BSTRIDE 136
#define ASZ (128 * ASTRIDE)
#define BSZ (32 * BSTRIDE)
#define TC_SMEM_BYTES (2 * (ASZ + BSZ) * 4)

template <int MODE>
__global__ __launch_bounds__(256)
void tc_gemm(const float* __restrict__ Bm,
             const float* __restrict__ bias,
             const float* __restrict__ aux,
             float* __restrict__ Cext)
{
    constexpr int Nn = (MODE == 2) ? C4 : CC;
    constexpr int Kk = (MODE == 3) ? C4 : CC;
    constexpr int NT = Kk / 32;
    const float* A = (MODE == 1) ? g_xo : (MODE == 2) ? g_ln2 : g_fc1;
    float* Cout    = (MODE == 1) ? g_x2 : (MODE == 2) ? g_fc1 : Cext;

    extern __shared__ float smem[];
    float* Abuf = smem;                  // [2][128][ASTRIDE]
    float* Bbuf = smem + 2 * ASZ;        // [2][32][BSTRIDE]

    int tid  = threadIdx.x;
    int lane = tid & 31;
    int wid  = tid >> 5;
    int bx   = blockIdx.x;
    int row0 = blockIdx.y * 128;

    int wm = (wid & 1) * 64;
    int wn = (wid >> 1) * 32;
    int fr = lane >> 2;
    int fc = lane & 3;

    int a_r = tid >> 3;            // 0..31
    int a_c = (tid & 7) << 2;      // 0..28

    uint32_t sA = (uint32_t)__cvta_generic_to_shared(Abuf);
    uint32_t sB = (uint32_t)__cvta_generic_to_shared(Bbuf);

    auto issue = [&](int kt, int buf) {
        int k0 = kt * 32;
        #pragma unroll
        for (int p = 0; p < 4; p++) {
            int r  = a_r + p * 32;
            int gr = row0 + r;
            uint32_t ok = (gr < MR) ? 16u : 0u;
            const float* src = A + (size_t)(ok ? gr : row0) * Kk + k0 + a_c;
            cp_async16(sA + (buf * ASZ + r * ASTRIDE + a_c) * 4, src, ok);
        }
        #pragma unroll
        for (int p = 0; p < 4; p++) {
            int idx = tid + p * 256;
            int r   = idx >> 5;
            int c   = (idx & 31) << 2;
            const float* src = Bm + (size_t)(k0 + r) * Nn + bx * 128 + c;
            cp_async16(sB + (buf * BSZ + r * BSTRIDE + c) * 4, src, 16u);
        }
        cp_commit();
    };

    float acc[4][4][4];
    #pragma unroll
    for (int i = 0; i < 4; i++)
        #pragma unroll
        for (int j = 0; j < 4; j++)
            #pragma unroll
            for (int q = 0; q < 4; q++) acc[i][j][q] = 0.0f;

    issue(0, 0);

    for (int kt = 0; kt < NT; kt++) {
        int buf = kt & 1;
        if (kt + 1 < NT) { issue(kt + 1, buf ^ 1); cp_wait<1>(); }
        else             { cp_wait<0>(); }
        __syncthreads();

        const float* As = Abuf + buf * ASZ;
        const float* Bs = Bbuf + buf * BSZ;

        #pragma unroll
        for (int sub = 0; sub < 4; sub++) {
            int kb = sub * 8;
            uint32_t a[4][4], b[4][2];
            #pragma unroll
            for (int i = 0; i < 4; i++) {
                int mr = wm + i * 16 + fr;
                a[i][0] = f2tf32(As[(mr    ) * ASTRIDE + kb + fc    ]);
                a[i][1] = f2tf32(As[(mr + 8) * ASTRIDE + kb + fc    ]);
                a[i][2] = f2tf32(As[(mr    ) * ASTRIDE + kb + fc + 4]);
                a[i][3] = f2tf32(As[(mr + 8) * ASTRIDE + kb + fc + 4]);
            }
            #pragma unroll
            for (int j = 0; j < 4; j++) {
                int nc = wn + j * 8 + fr;
                b[j][0] = f2tf32(Bs[(kb + fc    ) * BSTRIDE + nc]);
                b[j][1] = f2tf32(Bs[(kb + fc + 4) * BSTRIDE + nc]);
            }
            #pragma unroll
            for (int i = 0; i < 4; i++)
                #pragma unroll
                for (int j = 0; j < 4; j++)
                    asm volatile(
                        "mma.sync.aligned.m16n8k8.row.col.f32.tf32.tf32.f32 "
                        "{%0,%1,%2,%3}, {%4,%5,%6,%7}, {%8,%9}, {%0,%1,%2,%3};"
                        : "+f"(acc[i][j][0]), "+f"(acc[i][j][1]),
                          "+f"(acc[i][j][2]), "+f"(acc[i][j][3])
                        : "r"(a[i][0]), "r"(a[i][1]), "r"(a[i][2]), "r"(a[i][3]),
                          "r"(b[j][0]), "r"(b[j][1]));
        }
        __syncthreads();
    }

    // epilogue: c0,c1 at (row, col..col+1); c2,c3 at (row+8, ...)
    #pragma unroll
    for (int i = 0; i < 4; i++) {
        #pragma unroll
        for (int half = 0; half < 2; half++) {
            int row = row0 + wm + i * 16 + fr + half * 8;
            if (row >= MR) continue;
            float prow = 0.f;
            int   rmap = 0, bidx = 0;
            if (MODE == 1) { prow = g_pol[row]; rmap = g_rowmap[row]; bidx = row / NN; }
            if (MODE == 3) prow = g_pol[row];
            #pragma unroll
            for (int j = 0; j < 4; j++) {
                #pragma unroll
                for (int q = 0; q < 2; q++) {
                    int col = bx * 128 + wn + j * 8 + 2 * fc + q;
                    float a = acc[i][j][half * 2 + q];
                    size_t oidx = (size_t)row * Nn + col;
                    if (MODE == 1) {
                        float xg = (rmap >= 0)
                            ? aux[(size_t)(bidx * NN + rmap) * CC + col] : 0.0f;
                        Cout[oidx] = xg + (a + bias[col]) * prow;
                    } else if (MODE == 2) {
                        float tv = a + bias[col];
                        Cout[oidx] = tv * 0.5f * (1.0f + erff(tv * 0.70710678118654752f));
                    } else {
                        Cout[oidx] = (g_x2[oidx] + a + bias[col]) * prow;
                    }
                }
            }
        }
    }
}

// ---------------------------------------------------------------- QK^T * scale
__global__ __launch_bounds__(256)
void qk_kernel()
{
    int bh = blockIdx.x;
    int b  = bh / HH, h = bh - b * HH;
    int n0 = blockIdx.y * 64;
    int m0 = blockIdx.z * 64;

    __shared__ float Qs[64][68];
    __shared__ float Ks[64][68];
    int t = threadIdx.x;

    for (int e = t; e < 4096; e += 256) {
        int r = e >> 6, k = e & 63;
        int n = n0 + r;
        Qs[k][r] = (n < NN) ? g_qkv[(size_t)(b * NN + n) * C3 + h * HD + k] : 0.f;
        int m = m0 + r;
        Ks[k][r] = (m < NN) ? g_qkv[(size_t)(b * NN + m) * C3 + CC + h * HD + k] : 0.f;
    }
    __syncthreads();

    int tx = t & 15, ty = t >> 4;
    float acc[4][4];
    #pragma unroll
    for (int i = 0; i < 4; i++)
        #pragma unroll
        for (int j = 0; j < 4; j++) acc[i][j] = 0.f;

    #pragma unroll 8
    for (int k = 0; k < 64; k++) {
        float4 qa = *(const float4*)(&Qs[k][ty * 4]);
        float4 ka = *(const float4*)(&Ks[k][tx * 4]);
        float q[4] = {qa.x, qa.y, qa.z, qa.w};
        float kv[4] = {ka.x, ka.y, ka.z, ka.w};
        #pragma unroll
        for (int i = 0; i < 4; i++)
            #pragma unroll
            for (int j = 0; j < 4; j++)
                acc[i][j] = fmaf(q[i], kv[j], acc[i][j]);
    }

    #pragma unroll
    for (int i = 0; i < 4; i++) {
        int n = n0 + ty * 4 + i;
        if (n >= NN) continue;
        #pragma unroll
        for (int j = 0; j < 4; j++) {
            int m = m0 + tx * 4 + j;
            if (m < NN)
                g_attn[((size_t)bh * NN + n) * NN + m] = acc[i][j] * 0.125f;
        }
    }
}

// ---------------------------------------------------------------- softmax w/ policy + eps
__global__ void softmax_kernel(const float* __restrict__ policy)
{
    int bh = blockIdx.x;
    int n  = blockIdx.y * 8 + (threadIdx.x >> 5);
    if (n >= NN) return;
    int lane = threadIdx.x & 31;
    int b    = bh / HH;
    float* row = g_attn + ((size_t)bh * NN + n) * NN;

    float v[7];
    float mx = -1e30f;
    #pragma unroll
    for (int i = 0; i < 7; i++) {
        int m = lane + i * 32;
        v[i] = (m < NN) ? row[m] : -1e30f;
        mx = fmaxf(mx, v[i]);
    }
    #pragma unroll
    for (int o = 16; o > 0; o >>= 1) mx = fmaxf(mx, __shfl_xor_sync(0xffffffffu, mx, o));

    float s = 0.f;
    #pragma unroll
    for (int i = 0; i < 7; i++) {
        int m = lane + i * 32;
        if (m < NN) {
            float p = (m == n) ? 1.0f : policy[b * NN + m];
            v[i] = expf(v[i] - mx) * p;
            s += v[i];
        }
    }
    #pragma unroll
    for (int o = 16; o > 0; o >>= 1) s += __shfl_xor_sync(0xffffffffu, s, o);

    float inv = 1.0f / (s + 1e-6f);
    const float c = (float)(1e-6 / 197.0);
    #pragma unroll
    for (int i = 0; i < 7; i++) {
        int m = lane + i * 32;
        if (m < NN) row[m] = (v[i] + c) * inv;
    }
}

// ---------------------------------------------------------------- ATS sampling (fp64)
__global__ void sample_kernel(const float* __restrict__ policy)
{
    int b = blockIdx.x;
    int t = threadIdx.x;

    __shared__ double draw[NN];
    __shared__ double scacc[NN];
    __shared__ double scn[196], cdfs[196], ncdf[196];
    __shared__ int    ord[196], pick[196], spick[196], uu[196], uq[196];
    __shared__ double dred;
    __shared__ double dtmp[2];

    for (int m = t; m < NN; m += 256) scacc[m] = 0.0;
    __syncthreads();

    for (int h = 0; h < HH; h++) {
        for (int m = t; m < NN; m += 256) {
            const float* q0 = &g_qkv[(size_t)(b * NN) * C3 + h * HD];
            const float* km = &g_qkv[(size_t)(b * NN + m) * C3 + CC + h * HD];
            double s = 0.0;
            for (int d = 0; d < HD; d++) s += (double)q0[d] * (double)km[d];
            draw[m] = s * 0.125;
        }
        __syncthreads();
        if (t == 0) {
            double mx = draw[0];
            for (int m = 1; m < NN; m++) mx = (draw[m] > mx) ? draw[m] : mx;
            dred = mx;
        }
        __syncthreads();
        double mx = dred;
        for (int m = t; m < NN; m += 256) {
            double p = (m == 0) ? 1.0 : (double)policy[b * NN + m];
            draw[m] = exp(draw[m] - mx) * p;
        }
        __syncthreads();
        if (t == 0) {
            double s = 0.0;
            for (int m = 0; m < NN; m++) s += draw[m];
            dred = s + 1e-6;
        }
        __syncthreads();
        double den = dred;
        const double c = 1e-6 / 197.0;
        for (int m = t; m < NN; m += 256) scacc[m] += (draw[m] + c) / den;
        __syncthreads();
    }

    for (int j = t; j < 196; j += 256) {
        int m = j + 1;
        const float* v = &g_qkv[(size_t)(b * NN + m) * C3 + 2 * CC];
        double s = 0.0;
        for (int d = 0; d < CC; d++) { double x = v[d]; s += x * x; }
        scn[j] = scacc[m] * sqrt(s);
    }
    __syncthreads();
    if (t == 0) {
        double s = 0.0;
        for (int j = 0; j < 196; j++) s += scn[j];
        dtmp[0] = s;
    }
    __syncthreads();
    double ssum = dtmp[0];
    for (int j = t; j < 196; j += 256) scn[j] = scn[j] / ssum;
    __syncthreads();

    for (int j = t; j < 196; j += 256) {
        double sj = scn[j];
        int r = 0;
        for (int i = 0; i < 196; i++) {
            double si = scn[i];
            if (si < sj || (si == sj && i < j)) r++;
        }
        ord[r] = j;
    }
    __syncthreads();

    if (t == 0) {
        double c0 = 0.0;
        for (int r = 0; r < 196; r++) { c0 += scn[ord[r]]; cdfs[r] = c0; }
        double mn = cdfs[0], mx2 = cdfs[0];
        for (int r = 1; r < 196; r++) {
            double cv = cdfs[r];
            mn = cv < mn ? cv : mn;
            mx2 = cv > mx2 ? cv : mx2;
        }
        dtmp[0] = mn; dtmp[1] = mx2;
    }
    __syncthreads();
    double mn = dtmp[0], rng = dtmp[1] - dtmp[0];
    for (int r = t; r < 196; r += 256) ncdf[r] = (cdfs[r] - mn) / rng;
    __syncthreads();
    if (t == 0) {
        double ysmin = 1e18;
        for (int r = 0; r < 196; r++) {
            double v = ncdf[r] + ((ncdf[r] == 0.0) ? 1e8 : 0.0);
            ysmin = v < ysmin ? v : ysmin;
        }
        dtmp[0] = ysmin;
    }
    __syncthreads();
    double ys_start = dtmp[0];

    for (int i = t; i < 196; i += 256) {
        double lin = (i == 195) ? 1.0 : ((double)i * (1.0 / 195.0));
        double ys  = ys_start + (lin * 195.0 - ys_start * (double)i) / 195.0;
        double best = 1e30;
        int arg = 0;
        for (int j = 0; j < 196; j++) {
            double d2 = fabs(ys - ncdf[j]);
            if (d2 < best) { best = d2; arg = j; }
        }
        pick[i] = arg;
    }
    __syncthreads();

    for (int j = t; j < 196; j += 256) {
        int pj = pick[j];
        int r = 0;
        for (int i = 0; i < 196; i++) {
            int pi = pick[i];
            if (pi < pj || (pi == pj && i < j)) r++;
        }
        spick[r] = pj;
    }
    __syncthreads();
    for (int j = t; j < 196; j += 256) {
        int sl = (j < 195) ? spick[j + 1] : 1;
        uu[j] = (sl - spick[j] == 0) ? 196 : spick[j];
    }
    __syncthreads();
    for (int j = t; j < 196; j += 256) {
        int vj = uu[j];
        int r = 0;
        for (int i = 0; i < 196; i++) {
            int vi = uu[i];
            if (vi < vj || (vi == vj && i < j)) r++;
        }
        uq[r] = vj;
    }
    __syncthreads();

    if (t == 0) { g_rowmap[b * NN] = 0; g_pol[b * NN] = 1.0f; }
    for (int i = t; i < 196; i += 256) {
        int u = uq[i];
        g_pol[b * NN + 1 + i]    = (u != 196) ? 1.0f : 0.0f;
        g_rowmap[b * NN + 1 + i] = (u < 196) ? (1 + ord[u]) : -1;
    }
}

// ---------------------------------------------------------------- gathered attn @ V
__global__ __launch_bounds__(256)
void av_kernel()
{
    int bh = blockIdx.x;
    int b  = bh / HH, h = bh - b * HH;
    int n0 = blockIdx.y * 64;

    __shared__ float As[64][68];
    __shared__ float Vs[64][68];
    __shared__ int   rm[64];

    int t = threadIdx.x;
    if (t < 64) {
        int n = n0 + t;
        rm[t] = (n < NN) ? g_rowmap[b * NN + n] : -1;
    }
    __syncthreads();

    int tx = t & 15, ty = t >> 4;
    float acc[4][4];
    #pragma unroll
    for (int i = 0; i < 4; i++)
        #pragma unroll
        for (int j = 0; j < 4; j++) acc[i][j] = 0.f;

    for (int m0 = 0; m0 < NN; m0 += 64) {
        for (int e = t; e < 4096; e += 256) {
            int i = e >> 6, kk = e & 63;
            int r = rm[i];
            int m = m0 + kk;
            As[kk][i] = (r >= 0 && m < NN)
                ? g_attn[((size_t)bh * NN + r) * NN + m] : 0.f;
        }
        for (int e = t; e < 4096; e += 256) {
            int kk = e >> 6, d = e & 63;
            int m = m0 + kk;
            Vs[kk][d] = (m < NN)
                ? g_qkv[(size_t)(b * NN + m) * C3 + 2 * CC + h * HD + d] : 0.f;
        }
        __syncthreads();

        #pragma unroll 8
        for (int kk = 0; kk < 64; kk++) {
            float4 aa4 = *(const float4*)(&As[kk][ty * 4]);
            float4 vv4 = *(const float4*)(&Vs[kk][tx * 4]);
            float aa[4] = {aa4.x, aa4.y, aa4.z, aa4.w};
            float vv[4] = {vv4.x, vv4.y, vv4.z, vv4.w};
            #pragma unroll
            for (int i = 0; i < 4; i++)
                #pragma unroll
                for (int j = 0; j < 4; j++)
                    acc[i][j] = fmaf(aa[i], vv[j], acc[i][j]);
        }
        __syncthreads();
    }

    #pragma unroll
    for (int i = 0; i < 4; i++) {
        int n = n0 + ty * 4 + i;
        if (n >= NN) continue;
        #pragma unroll
        for (int j = 0; j < 4; j++)
            g_xo[(size_t)(b * NN + n) * CC + h * HD + tx * 4 + j] = acc[i][j];
    }
}

// ---------------------------------------------------------------- launch
extern "C" void kernel_launch(void* const* d_in, const int* in_sizes, int n_in,
                              void* d_out, int out_size)
{
    const float* x      = (const float*)d_in[0];
    const float* policy = (const float*)d_in[1];
    const float* w_qkv  = (const float*)d_in[2];
    const float* w_proj = (const float*)d_in[3];
    const float* b_proj = (const float*)d_in[4];
    const float* g1     = (const float*)d_in[5];
    const float* b1     = (const float*)d_in[6];
    const float* g2     = (const float*)d_in[7];
    const float* b2     = (const float*)d_in[8];
    const float* w_fc1  = (const float*)d_in[9];
    const float* b_fc1  = (const float*)d_in[10];
    const float* w_fc2  = (const float*)d_in[11];
    const float* b_fc2  = (const float*)d_in[12];
    float* out = (float*)d_out;

    cudaFuncSetAttribute(tc_gemm<1>, cudaFuncAttributeMaxDynamicSharedMemorySize, TC_SMEM_BYTES);
    cudaFuncSetAttribute(tc_gemm<2>, cudaFuncAttributeMaxDynamicSharedMemorySize, TC_SMEM_BYTES);
    cudaFuncSetAttribute(tc_gemm<3>, cudaFuncAttributeMaxDynamicSharedMemorySize, TC_SMEM_BYTES);

    const int MTILES = (MR + 127) / 128;   // 99

    // 1. LN1
    ln_kernel<<<MR, 256>>>(x, g1, b1, 0);
    // 2. QKV GEMM: fp32, pipelined (feeds the discrete sampling path)
    sgemm_qkv<<<dim3(C3 / 128, MTILES), 256>>>(w_qkv, policy);
    // 3. Q K^T * scale
    qk_kernel<<<dim3(BH, 4, 4), 256>>>();
    // 4. softmax with policy + eps smoothing (in place)
    softmax_kernel<<<dim3(BH, 25), 256>>>(policy);
    // 5. ATS sampling (fp64 critical path) -> rowmap / pol
    sample_kernel<<<BB, 256>>>(policy);
    // 6. gathered attn @ V
    av_kernel<<<dim3(BH, 4), 256>>>();
    // 7. proj GEMM (TF32 TC, pipelined) + bias, *pol, + gathered x residual -> x2
    tc_gemm<1><<<dim3(CC / 128, MTILES), 256, TC_SMEM_BYTES>>>(w_proj, b_proj, x, nullptr);
    // 8. LN2
    ln_kernel<<<MR, 256>>>(nullptr, g2, b2, 1);
    // 9. FC1 GEMM (TF32 TC, pipelined) + exact GELU
    tc_gemm<2><<<dim3(C4 / 128, MTILES), 256, TC_SMEM_BYTES>>>(w_fc1, b_fc1, nullptr, nullptr);
    // 10. FC2 GEMM (TF32 TC, pipelined) + residual + *pol -> out
    tc_gemm<3><<<dim3(CC / 128, MTILES), 256, TC_SMEM_BYTES>>>(w_fc2, b_fc2, nullptr, out);
}

// round 15
// speedup vs baseline: 1.5181x; 1.5181x over previous
#include <cuda_runtime.h>
#include <math.h>
#include <stdint.h>

// ---------------------------------------------------------------- constants
#define BB 64
#define NN 197
#define CC 768
#define HH 12
#define HD 64
#define C3 2304
#define C4 3072
#define MR (BB*NN)        /* 12608 rows */
#define BH (BB*HH)        /* 768 (b,h) pairs */
#define LN_EPS 1e-5f

// ---------------------------------------------------------------- scratch
__device__ __align__(16) float g_xn  [(size_t)MR * CC];
__device__ __align__(16) float g_qkv [(size_t)MR * C3];
__device__ __align__(16) float g_attn[(size_t)BH * NN * NN];
__device__ __align__(16) float g_xo  [(size_t)MR * CC];
__device__ __align__(16) float g_x2  [(size_t)MR * CC];
__device__ __align__(16) float g_ln2 [(size_t)MR * CC];
__device__ __align__(16) float g_fc1 [(size_t)MR * C4];
__device__ int   g_rowmap[MR];
__device__ float g_pol   [MR];

// ---------------------------------------------------------------- helpers
__device__ __forceinline__ uint32_t f2tf32(float x) {
    uint32_t u;
    asm("cvt.rna.tf32.f32 %0, %1;" : "=r"(u) : "f"(x));
    return u;
}

// ---------------------------------------------------------------- LayerNorm
__global__ void ln_kernel(const float* __restrict__ Xin,
                          const float* __restrict__ gam,
                          const float* __restrict__ bet,
                          int mode)
{
    const float* X = (mode == 0) ? Xin : g_x2;
    float*       Y = (mode == 0) ? g_xn : g_ln2;

    __shared__ float red[40];
    int row = blockIdx.x;
    int t   = threadIdx.x;
    const float* x = X + (size_t)row * CC;

    float v0 = x[t], v1 = x[t + 256], v2 = x[t + 512];

    float s = v0 + v1 + v2;
    #pragma unroll
    for (int o = 16; o > 0; o >>= 1) s += __shfl_xor_sync(0xffffffffu, s, o);
    if ((t & 31) == 0) red[t >> 5] = s;
    __syncthreads();
    if (t < 32) {
        float r = (t < 8) ? red[t] : 0.0f;
        #pragma unroll
        for (int o = 4; o > 0; o >>= 1) r += __shfl_xor_sync(0xffffffffu, r, o);
        if (t == 0) red[32] = r;
    }
    __syncthreads();
    float mean = red[32] * (1.0f / 768.0f);
    __syncthreads();

    float d0 = v0 - mean, d1 = v1 - mean, d2 = v2 - mean;
    s = d0 * d0 + d1 * d1 + d2 * d2;
    #pragma unroll
    for (int o = 16; o > 0; o >>= 1) s += __shfl_xor_sync(0xffffffffu, s, o);
    if ((t & 31) == 0) red[t >> 5] = s;
    __syncthreads();
    if (t < 32) {
        float r = (t < 8) ? red[t] : 0.0f;
        #pragma unroll
        for (int o = 4; o > 0; o >>= 1) r += __shfl_xor_sync(0xffffffffu, r, o);
        if (t == 0) red[33] = r;
    }
    __syncthreads();
    float var  = red[33] * (1.0f / 768.0f);
    float rstd = 1.0f / sqrtf(var + LN_EPS);

    float* y = Y + (size_t)row * CC;
    y[t]       = d0 * rstd * gam[t]       + bet[t];
    y[t + 256] = d1 * rstd * gam[t + 256] + bet[t + 256];
    y[t + 512] = d2 * rstd * gam[t + 512] + bet[t + 512];
}

// ---------------------------------------------------------------- fp32 SGEMM (QKV) — R10 verbatim
// g_xn @ w_qkv(768x2304) -> g_qkv ; epilogue: * policy[row]
// MUST stay fp32: qkv feeds the discrete sampling path.
__global__ __launch_bounds__(256)
void sgemm_qkv(const float* __restrict__ Bm, const float* __restrict__ policy)
{
    const int Nn = C3, Kk = CC;
    const float* A = g_xn;
    float* Cout = g_qkv;

    __shared__ float As[16][128];
    __shared__ float Bs[16][128];

    int tid  = threadIdx.x;
    int bx   = blockIdx.x;
    int row0 = blockIdx.y * 128;
    int tx   = tid & 15;
    int ty   = tid >> 4;

    int a_r = tid >> 2;
    int a_c = (tid & 3) << 2;
    int b_r = tid >> 5;
    int b_c = (tid & 31) << 2;

    float acc[8][8];
    #pragma unroll
    for (int i = 0; i < 8; i++)
        #pragma unroll
        for (int j = 0; j < 8; j++) acc[i][j] = 0.0f;

    for (int k0 = 0; k0 < Kk; k0 += 16) {
        #pragma unroll
        for (int p = 0; p < 2; p++) {
            int r = row0 + a_r + p * 64;
            float4 v = (r < MR)
                ? *(const float4*)(A + (size_t)r * Kk + k0 + a_c)
                : make_float4(0.f, 0.f, 0.f, 0.f);
            As[a_c + 0][a_r + p * 64] = v.x;
            As[a_c + 1][a_r + p * 64] = v.y;
            As[a_c + 2][a_r + p * 64] = v.z;
            As[a_c + 3][a_r + p * 64] = v.w;
        }
        #pragma unroll
        for (int p = 0; p < 2; p++) {
            int kr = k0 + b_r + p * 8;
            *(float4*)(&Bs[b_r + p * 8][b_c]) =
                *(const float4*)(Bm + (size_t)kr * Nn + bx * 128 + b_c);
        }
        __syncthreads();

        #pragma unroll
        for (int k = 0; k < 16; k++) {
            float af[8], bf[8];
            *(float4*)(af)     = *(const float4*)(&As[k][ty * 4]);
            *(float4*)(af + 4) = *(const float4*)(&As[k][ty * 4 + 64]);
            *(float4*)(bf)     = *(const float4*)(&Bs[k][tx * 4]);
            *(float4*)(bf + 4) = *(const float4*)(&Bs[k][tx * 4 + 64]);
            #pragma unroll
            for (int i = 0; i < 8; i++)
                #pragma unroll
                for (int j = 0; j < 8; j++)
                    acc[i][j] = fmaf(af[i], bf[j], acc[i][j]);
        }
        __syncthreads();
    }

    #pragma unroll
    for (int i = 0; i < 8; i++) {
        int row = row0 + ty * 4 + ((i & 4) ? 64 : 0) + (i & 3);
        if (row >= MR) continue;
        float prow = policy[row];
        #pragma unroll
        for (int j = 0; j < 8; j++) {
            int col = bx * 128 + tx * 4 + ((j & 4) ? 64 : 0) + (j & 3);
            Cout[(size_t)row * Nn + col] = acc[i][j] * prow;
        }
    }
}

// ---------------------------------------------------------------- TF32 tensor-core GEMM — R10 verbatim
// 128x128x32 tile, 8 warps x (64x32), mma.m16n8k8 tf32 (cvt.rna at smem fill).
// MODE 1: g_xo  @ Bm(768x768)  -> g_x2  ; epi: xgather + (acc+b)*pol  (aux = x)
// MODE 2: g_ln2 @ Bm(768x3072) -> g_fc1 ; epi: exact GELU(acc+b)
// MODE 3: g_fc1 @ Bm(3072x768) -> Cext  ; epi: (g_x2 + acc + b)*pol
template <int MODE>
__global__ __launch_bounds__(256, 2)
void tf32_gemm(const float* __restrict__ Bm,
               const float* __restrict__ bias,
               const float* __restrict__ aux,
               float* __restrict__ Cext)
{
    constexpr int Nn = (MODE == 2) ? C4 : CC;
    constexpr int Kk = (MODE == 3) ? C4 : CC;
    const float* A = (MODE == 1) ? g_xo : (MODE == 2) ? g_ln2 : g_fc1;
    float* Cout    = (MODE == 1) ? g_x2 : (MODE == 2) ? g_fc1 : Cext;

    __shared__ uint32_t As[128][36];   // [m][k], conflict-free
    __shared__ uint32_t Bs[32][136];   // [k][n], conflict-free

    int tid  = threadIdx.x;
    int lane = tid & 31;
    int wid  = tid >> 5;
    int bx   = blockIdx.x;
    int row0 = blockIdx.y * 128;

    int wm = (wid & 1) * 64;
    int wn = (wid >> 1) * 32;
    int fr = lane >> 2;
    int fc = lane & 3;

    float acc[4][4][4];
    #pragma unroll
    for (int i = 0; i < 4; i++)
        #pragma unroll
        for (int j = 0; j < 4; j++)
            #pragma unroll
            for (int q = 0; q < 4; q++) acc[i][j][q] = 0.0f;

    for (int k0 = 0; k0 < Kk; k0 += 32) {
        #pragma unroll
        for (int p = 0; p < 4; p++) {
            int idx = tid + p * 256;
            int r   = idx >> 3;
            int c   = (idx & 7) << 2;
            int gr  = row0 + r;
            float4 v = (gr < MR)
                ? *(const float4*)(A + (size_t)gr * Kk + k0 + c)
                : make_float4(0.f, 0.f, 0.f, 0.f);
            As[r][c + 0] = f2tf32(v.x);
            As[r][c + 1] = f2tf32(v.y);
            As[r][c + 2] = f2tf32(v.z);
            As[r][c + 3] = f2tf32(v.w);
        }
        #pragma unroll
        for (int p = 0; p < 4; p++) {
            int idx = tid + p * 256;
            int kr  = idx >> 5;
            int c   = (idx & 31) << 2;
            float4 v = *(const float4*)(Bm + (size_t)(k0 + kr) * Nn + bx * 128 + c);
            Bs[kr][c + 0] = f2tf32(v.x);
            Bs[kr][c + 1] = f2tf32(v.y);
            Bs[kr][c + 2] = f2tf32(v.z);
            Bs[kr][c + 3] = f2tf32(v.w);
        }
        __syncthreads();

        #pragma unroll
        for (int sub = 0; sub < 4; sub++) {
            int kb = sub * 8;
            uint32_t a[4][4], b[4][2];
            #pragma unroll
            for (int i = 0; i < 4; i++) {
                int mr = wm + i * 16 + fr;
                a[i][0] = As[mr    ][kb + fc    ];
                a[i][1] = As[mr + 8][kb + fc    ];
                a[i][2] = As[mr    ][kb + fc + 4];
                a[i][3] = As[mr + 8][kb + fc + 4];
            }
            #pragma unroll
            for (int j = 0; j < 4; j++) {
                int nc = wn + j * 8 + fr;
                b[j][0] = Bs[kb + fc    ][nc];
                b[j][1] = Bs[kb + fc + 4][nc];
            }
            #pragma unroll
            for (int i = 0; i < 4; i++)
                #pragma unroll
                for (int j = 0; j < 4; j++)
                    asm volatile(
                        "mma.sync.aligned.m16n8k8.row.col.f32.tf32.tf32.f32 "
                        "{%0,%1,%2,%3}, {%4,%5,%6,%7}, {%8,%9}, {%0,%1,%2,%3};"
                        : "+f"(acc[i][j][0]), "+f"(acc[i][j][1]),
                          "+f"(acc[i][j][2]), "+f"(acc[i][j][3])
                        : "r"(a[i][0]), "r"(a[i][1]), "r"(a[i][2]), "r"(a[i][3]),
                          "r"(b[j][0]), "r"(b[j][1]));
        }
        __syncthreads();
    }

    #pragma unroll
    for (int i = 0; i < 4; i++) {
        #pragma unroll
        for (int half = 0; half < 2; half++) {
            int row = row0 + wm + i * 16 + fr + half * 8;
            if (row >= MR) continue;
            float prow = 0.f;
            int   rmap = 0, bidx = 0;
            if (MODE == 1) { prow = g_pol[row]; rmap = g_rowmap[row]; bidx = row / NN; }
            if (MODE == 3) prow = g_pol[row];
            #pragma unroll
            for (int j = 0; j < 4; j++) {
                #pragma unroll
                for (int q = 0; q < 2; q++) {
                    int col = bx * 128 + wn + j * 8 + 2 * fc + q;
                    float a = acc[i][j][half * 2 + q];
                    size_t oidx = (size_t)row * Nn + col;
                    if (MODE == 1) {
                        float xg = (rmap >= 0)
                            ? aux[(size_t)(bidx * NN + rmap) * CC + col] : 0.0f;
                        Cout[oidx] = xg + (a + bias[col]) * prow;
                    } else if (MODE == 2) {
                        float tv = a + bias[col];
                        Cout[oidx] = tv * 0.5f * (1.0f + erff(tv * 0.70710678118654752f));
                    } else {
                        Cout[oidx] = (g_x2[oidx] + a + bias[col]) * prow;
                    }
                }
            }
        }
    }
}

// ---------------------------------------------------------------- fused QK^T + softmax
// One block = (bh, 64-row band). Computes the full 197-wide score row into smem,
// applies softmax-with-policy there, writes g_attn ONCE (saves softmax's full
// 119MB read + 119MB write of g_attn, and one launch).
// FIX vs R14: the score store is guarded (col < 200); the last m-tile spans
// columns up to 255, which previously corrupted neighbor rows and overflowed
// the 64x200 S buffer (illegal memory access).
#define QKS_SMEM ((2*64*68 + 64*200) * 4)   /* 84 KB dynamic */

__global__ __launch_bounds__(256)
void qks_kernel(const float* __restrict__ policy)
{
    extern __shared__ float sm[];
    float* Qs = sm;               // [64][68]  (k-major: Qs[k][r])
    float* Ks = sm + 64 * 68;     // [64][68]
    float* S  = sm + 2 * 64 * 68; // [64][200] score rows

    int bh = blockIdx.x;
    int b  = bh / HH, h = bh - b * HH;
    int n0 = blockIdx.y * 64;
    int t  = threadIdx.x;
    int tx = t & 15, ty = t >> 4;

    // Q band load (once)
    for (int e = t; e < 4096; e += 256) {
        int r = e >> 6, k = e & 63;
        int n = n0 + r;
        Qs[k * 68 + r] = (n < NN) ? g_qkv[(size_t)(b * NN + n) * C3 + h * HD + k] : 0.f;
    }

    // stream K tiles, accumulate scores into S
    for (int m0 = 0; m0 < NN; m0 += 64) {
        if (m0) __syncthreads();   // prior compute must finish reading Ks
        for (int e = t; e < 4096; e += 256) {
            int r = e >> 6, k = e & 63;
            int m = m0 + r;
            Ks[k * 68 + r] = (m < NN) ? g_qkv[(size_t)(b * NN + m) * C3 + CC + h * HD + k] : 0.f;
        }
        __syncthreads();           // covers the Q load on the first iteration too

        float acc[4][4];
        #pragma unroll
        for (int i = 0; i < 4; i++)
            #pragma unroll
            for (int j = 0; j < 4; j++) acc[i][j] = 0.f;

        #pragma unroll 8
        for (int k = 0; k < 64; k++) {
            float4 qa = *(const float4*)(&Qs[k * 68 + ty * 4]);
            float4 ka = *(const float4*)(&Ks[k * 68 + tx * 4]);
            float q[4]  = {qa.x, qa.y, qa.z, qa.w};
            float kv[4] = {ka.x, ka.y, ka.z, ka.w};
            #pragma unroll
            for (int i = 0; i < 4; i++)
                #pragma unroll
                for (int j = 0; j < 4; j++)
                    acc[i][j] = fmaf(q[i], kv[j], acc[i][j]);
        }

        #pragma unroll
        for (int i = 0; i < 4; i++)
            #pragma unroll
            for (int j = 0; j < 4; j++) {
                int col = m0 + tx * 4 + j;
                if (col < 200)      // FIX: guard last m-tile (cols 197..255)
                    S[(ty * 4 + i) * 200 + col] = acc[i][j] * 0.125f;
            }
    }
    __syncthreads();

    // softmax with policy + eps smoothing: one warp per row (8 rows/warp)
    int w = t >> 5, lane = t & 31;
    for (int r = w; r < 64; r += 8) {
        int n = n0 + r;
        if (n >= NN) break;        // r uniform per warp -> no divergence inside warp
        const float* row = &S[r * 200];

        float v[7];
        float mx = -1e30f;
        #pragma unroll
        for (int i = 0; i < 7; i++) {
            int m = lane + i * 32;
            v[i] = (m < NN) ? row[m] : -1e30f;
            mx = fmaxf(mx, v[i]);
        }
        #pragma unroll
        for (int o = 16; o > 0; o >>= 1) mx = fmaxf(mx, __shfl_xor_sync(0xffffffffu, mx, o));

        float s = 0.f;
        #pragma unroll
        for (int i = 0; i < 7; i++) {
            int m = lane + i * 32;
            if (m < NN) {
                float p = (m == n) ? 1.0f : policy[b * NN + m];
                v[i] = expf(v[i] - mx) * p;
                s += v[i];
            }
        }
        #pragma unroll
        for (int o = 16; o > 0; o >>= 1) s += __shfl_xor_sync(0xffffffffu, s, o);

        float inv = 1.0f / (s + 1e-6f);
        const float c = (float)(1e-6 / 197.0);
        float* orow = g_attn + ((size_t)bh * NN + n) * NN;
        #pragma unroll
        for (int i = 0; i < 7; i++) {
            int m = lane + i * 32;
            if (m < NN) orow[m] = (v[i] + c) * inv;
        }
    }
}

// ---------------------------------------------------------------- ATS sampling (fp64)
__global__ void sample_kernel(const float* __restrict__ policy)
{
    int b = blockIdx.x;
    int t = threadIdx.x;

    __shared__ double draw[NN];
    __shared__ double scacc[NN];
    __shared__ double scn[196], cdfs[196], ncdf[196];
    __shared__ int    ord[196], pick[196], spick[196], uu[196], uq[196];
    __shared__ double dred;
    __shared__ double dtmp[2];

    for (int m = t; m < NN; m += 256) scacc[m] = 0.0;
    __syncthreads();

    for (int h = 0; h < HH; h++) {
        for (int m = t; m < NN; m += 256) {
            const float* q0 = &g_qkv[(size_t)(b * NN) * C3 + h * HD];
            const float* km = &g_qkv[(size_t)(b * NN + m) * C3 + CC + h * HD];
            double s = 0.0;
            for (int d = 0; d < HD; d++) s += (double)q0[d] * (double)km[d];
            draw[m] = s * 0.125;
        }
        __syncthreads();
        if (t == 0) {
            double mx = draw[0];
            for (int m = 1; m < NN; m++) mx = (draw[m] > mx) ? draw[m] : mx;
            dred = mx;
        }
        __syncthreads();
        double mx = dred;
        for (int m = t; m < NN; m += 256) {
            double p = (m == 0) ? 1.0 : (double)policy[b * NN + m];
            draw[m] = exp(draw[m] - mx) * p;
        }
        __syncthreads();
        if (t == 0) {
            double s = 0.0;
            for (int m = 0; m < NN; m++) s += draw[m];
            dred = s + 1e-6;
        }
        __syncthreads();
        double den = dred;
        const double c = 1e-6 / 197.0;
        for (int m = t; m < NN; m += 256) scacc[m] += (draw[m] + c) / den;
        __syncthreads();
    }

    for (int j = t; j < 196; j += 256) {
        int m = j + 1;
        const float* v = &g_qkv[(size_t)(b * NN + m) * C3 + 2 * CC];
        double s = 0.0;
        for (int d = 0; d < CC; d++) { double x = v[d]; s += x * x; }
        scn[j] = scacc[m] * sqrt(s);
    }
    __syncthreads();
    if (t == 0) {
        double s = 0.0;
        for (int j = 0; j < 196; j++) s += scn[j];
        dtmp[0] = s;
    }
    __syncthreads();
    double ssum = dtmp[0];
    for (int j = t; j < 196; j += 256) scn[j] = scn[j] / ssum;
    __syncthreads();

    for (int j = t; j < 196; j += 256) {
        double sj = scn[j];
        int r = 0;
        for (int i = 0; i < 196; i++) {
            double si = scn[i];
            if (si < sj || (si == sj && i < j)) r++;
        }
        ord[r] = j;
    }
    __syncthreads();

    if (t == 0) {
        double c0 = 0.0;
        for (int r = 0; r < 196; r++) { c0 += scn[ord[r]]; cdfs[r] = c0; }
        double mn = cdfs[0], mx2 = cdfs[0];
        for (int r = 1; r < 196; r++) {
            double cv = cdfs[r];
            mn = cv < mn ? cv : mn;
            mx2 = cv > mx2 ? cv : mx2;
        }
        dtmp[0] = mn; dtmp[1] = mx2;
    }
    __syncthreads();
    double mn = dtmp[0], rng = dtmp[1] - dtmp[0];
    for (int r = t; r < 196; r += 256) ncdf[r] = (cdfs[r] - mn) / rng;
    __syncthreads();
    if (t == 0) {
        double ysmin = 1e18;
        for (int r = 0; r < 196; r++) {
            double v = ncdf[r] + ((ncdf[r] == 0.0) ? 1e8 : 0.0);
            ysmin = v < ysmin ? v : ysmin;
        }
        dtmp[0] = ysmin;
    }
    __syncthreads();
    double ys_start = dtmp[0];

    for (int i = t; i < 196; i += 256) {
        double lin = (i == 195) ? 1.0 : ((double)i * (1.0 / 195.0));
        double ys  = ys_start + (lin * 195.0 - ys_start * (double)i) / 195.0;
        double best = 1e30;
        int arg = 0;
        for (int j = 0; j < 196; j++) {
            double d2 = fabs(ys - ncdf[j]);
            if (d2 < best) { best = d2; arg = j; }
        }
        pick[i] = arg;
    }
    __syncthreads();

    for (int j = t; j < 196; j += 256) {
        int pj = pick[j];
        int r = 0;
        for (int i = 0; i < 196; i++) {
            int pi = pick[i];
            if (pi < pj || (pi == pj && i < j)) r++;
        }
        spick[r] = pj;
    }
    __syncthreads();
    for (int j = t; j < 196; j += 256) {
        int sl = (j < 195) ? spick[j + 1] : 1;
        uu[j] = (sl - spick[j] == 0) ? 196 : spick[j];
    }
    __syncthreads();
    for (int j = t; j < 196; j += 256) {
        int vj = uu[j];
        int r = 0;
        for (int i = 0; i < 196; i++) {
            int vi = uu[i];
            if (vi < vj || (vi == vj && i < j)) r++;
        }
        uq[r] = vj;
    }
    __syncthreads();

    if (t == 0) { g_rowmap[b * NN] = 0; g_pol[b * NN] = 1.0f; }
    for (int i = t; i < 196; i += 256) {
        int u = uq[i];
        g_pol[b * NN + 1 + i]    = (u != 196) ? 1.0f : 0.0f;
        g_rowmap[b * NN + 1 + i] = (u < 196) ? (1 + ord[u]) : -1;
    }
}

// ---------------------------------------------------------------- gathered attn @ V
__global__ __launch_bounds__(256)
void av_kernel()
{
    int bh = blockIdx.x;
    int b  = bh / HH, h = bh - b * HH;
    int n0 = blockIdx.y * 64;

    __shared__ float As[64][68];
    __shared__ float Vs[64][68];
    __shared__ int   rm[64];

    int t = threadIdx.x;
    if (t < 64) {
        int n = n0 + t;
        rm[t] = (n < NN) ? g_rowmap[b * NN + n] : -1;
    }
    __syncthreads();

    int tx = t & 15, ty = t >> 4;
    float acc[4][4];
    #pragma unroll
    for (int i = 0; i < 4; i++)
        #pragma unroll
        for (int j = 0; j < 4; j++) acc[i][j] = 0.f;

    for (int m0 = 0; m0 < NN; m0 += 64) {
        for (int e = t; e < 4096; e += 256) {
            int i = e >> 6, kk = e & 63;
            int r = rm[i];
            int m = m0 + kk;
            As[kk][i] = (r >= 0 && m < NN)
                ? g_attn[((size_t)bh * NN + r) * NN + m] : 0.f;
        }
        for (int e = t; e < 4096; e += 256) {
            int kk = e >> 6, d = e & 63;
            int m = m0 + kk;
            Vs[kk][d] = (m < NN)
                ? g_qkv[(size_t)(b * NN + m) * C3 + 2 * CC + h * HD + d] : 0.f;
        }
        __syncthreads();

        #pragma unroll 8
        for (int kk = 0; kk < 64; kk++) {
            float4 aa4 = *(const float4*)(&As[kk][ty * 4]);
            float4 vv4 = *(const float4*)(&Vs[kk][tx * 4]);
            float aa[4] = {aa4.x, aa4.y, aa4.z, aa4.w};
            float vv[4] = {vv4.x, vv4.y, vv4.z, vv4.w};
            #pragma unroll
            for (int i = 0; i < 4; i++)
                #pragma unroll
                for (int j = 0; j < 4; j++)
                    acc[i][j] = fmaf(aa[i], vv[j], acc[i][j]);
        }
        __syncthreads();
    }

    #pragma unroll
    for (int i = 0; i < 4; i++) {
        int n = n0 + ty * 4 + i;
        if (n >= NN) continue;
        #pragma unroll
        for (int j = 0; j < 4; j++)
            g_xo[(size_t)(b * NN + n) * CC + h * HD + tx * 4 + j] = acc[i][j];
    }
}

// ---------------------------------------------------------------- launch
extern "C" void kernel_launch(void* const* d_in, const int* in_sizes, int n_in,
                              void* d_out, int out_size)
{
    const float* x      = (const float*)d_in[0];
    const float* policy = (const float*)d_in[1];
    const float* w_qkv  = (const float*)d_in[2];
    const float* w_proj = (const float*)d_in[3];
    const float* b_proj = (const float*)d_in[4];
    const float* g1     = (const float*)d_in[5];
    const float* b1     = (const float*)d_in[6];
    const float* g2     = (const float*)d_in[7];
    const float* b2     = (const float*)d_in[8];
    const float* w_fc1  = (const float*)d_in[9];
    const float* b_fc1  = (const float*)d_in[10];
    const float* w_fc2  = (const float*)d_in[11];
    const float* b_fc2  = (const float*)d_in[12];
    float* out = (float*)d_out;

    cudaFuncSetAttribute(qks_kernel, cudaFuncAttributeMaxDynamicSharedMemorySize, QKS_SMEM);

    const int MTILES = (MR + 127) / 128;   // 99

    // 1. LN1
    ln_kernel<<<MR, 256>>>(x, g1, b1, 0);
    // 2. QKV GEMM: fp32 (feeds the discrete sampling path) — R10 verbatim
    sgemm_qkv<<<dim3(C3 / 128, MTILES), 256>>>(w_qkv, policy);
    // 3. fused Q K^T * scale + softmax-with-policy -> g_attn (single write)
    qks_kernel<<<dim3(BH, 4), 256, QKS_SMEM>>>(policy);
    // 4. ATS sampling (fp64 critical path) -> rowmap / pol
    sample_kernel<<<BB, 256>>>(policy);
    // 5. gathered attn @ V
    av_kernel<<<dim3(BH, 4), 256>>>();
    // 6. proj GEMM (TF32 TC) + bias, *pol, + gathered x residual -> x2 — R10 verbatim
    tf32_gemm<1><<<dim3(CC / 128, MTILES), 256>>>(w_proj, b_proj, x, nullptr);
    // 7. LN2
    ln_kernel<<<MR, 256>>>(nullptr, g2, b2, 1);
    // 8. FC1 GEMM (TF32 TC) + exact GELU — R10 verbatim
    tf32_gemm<2><<<dim3(C4 / 128, MTILES), 256>>>(w_fc1, b_fc1, nullptr, nullptr);
    // 9. FC2 GEMM (TF32 TC) + residual + *pol -> out — R10 verbatim
    tf32_gemm<3><<<dim3(CC / 128, MTILES), 256>>>(w_fc2, b_fc2, nullptr, out);
}

// round 16
// speedup vs baseline: 1.6576x; 1.0919x over previous
#include <cuda_runtime.h>
#include <math.h>
#include <stdint.h>

// ---------------------------------------------------------------- constants
#define BB 64
#define NN 197
#define CC 768
#define HH 12
#define HD 64
#define C3 2304
#define C4 3072
#define MR (BB*NN)        /* 12608 rows */
#define BH (BB*HH)        /* 768 (b,h) pairs */
#define LN_EPS 1e-5f

// ---------------------------------------------------------------- scratch
__device__ __align__(16) float g_xn  [(size_t)MR * CC];
__device__ __align__(16) float g_qkv [(size_t)MR * C3];
__device__ __align__(16) float g_attn[(size_t)BH * NN * NN];
__device__ __align__(16) float g_xo  [(size_t)MR * CC];
__device__ __align__(16) float g_x2  [(size_t)MR * CC];
__device__ __align__(16) float g_ln2 [(size_t)MR * CC];
__device__ __align__(16) float g_fc1 [(size_t)MR * C4];
__device__ int   g_rowmap[MR];
__device__ float g_pol   [MR];

// ---------------------------------------------------------------- helpers
__device__ __forceinline__ uint32_t f2tf32(float x) {
    uint32_t u;
    asm("cvt.rna.tf32.f32 %0, %1;" : "=r"(u) : "f"(x));
    return u;
}

// ---------------------------------------------------------------- LayerNorm
__global__ void ln_kernel(const float* __restrict__ Xin,
                          const float* __restrict__ gam,
                          const float* __restrict__ bet,
                          int mode)
{
    const float* X = (mode == 0) ? Xin : g_x2;
    float*       Y = (mode == 0) ? g_xn : g_ln2;

    __shared__ float red[40];
    int row = blockIdx.x;
    int t   = threadIdx.x;
    const float* x = X + (size_t)row * CC;

    float v0 = x[t], v1 = x[t + 256], v2 = x[t + 512];

    float s = v0 + v1 + v2;
    #pragma unroll
    for (int o = 16; o > 0; o >>= 1) s += __shfl_xor_sync(0xffffffffu, s, o);
    if ((t & 31) == 0) red[t >> 5] = s;
    __syncthreads();
    if (t < 32) {
        float r = (t < 8) ? red[t] : 0.0f;
        #pragma unroll
        for (int o = 4; o > 0; o >>= 1) r += __shfl_xor_sync(0xffffffffu, r, o);
        if (t == 0) red[32] = r;
    }
    __syncthreads();
    float mean = red[32] * (1.0f / 768.0f);
    __syncthreads();

    float d0 = v0 - mean, d1 = v1 - mean, d2 = v2 - mean;
    s = d0 * d0 + d1 * d1 + d2 * d2;
    #pragma unroll
    for (int o = 16; o > 0; o >>= 1) s += __shfl_xor_sync(0xffffffffu, s, o);
    if ((t & 31) == 0) red[t >> 5] = s;
    __syncthreads();
    if (t < 32) {
        float r = (t < 8) ? red[t] : 0.0f;
        #pragma unroll
        for (int o = 4; o > 0; o >>= 1) r += __shfl_xor_sync(0xffffffffu, r, o);
        if (t == 0) red[33] = r;
    }
    __syncthreads();
    float var  = red[33] * (1.0f / 768.0f);
    float rstd = 1.0f / sqrtf(var + LN_EPS);

    float* y = Y + (size_t)row * CC;
    y[t]       = d0 * rstd * gam[t]       + bet[t];
    y[t + 256] = d1 * rstd * gam[t + 256] + bet[t + 256];
    y[t + 512] = d2 * rstd * gam[t + 512] + bet[t + 512];
}

// ---------------------------------------------------------------- fp32 SGEMM (QKV) — R10 verbatim
// g_xn @ w_qkv(768x2304) -> g_qkv ; epilogue: * policy[row]
// MUST stay fp32: qkv feeds the discrete sampling path.
__global__ __launch_bounds__(256)
void sgemm_qkv(const float* __restrict__ Bm, const float* __restrict__ policy)
{
    const int Nn = C3, Kk = CC;
    const float* A = g_xn;
    float* Cout = g_qkv;

    __shared__ float As[16][128];
    __shared__ float Bs[16][128];

    int tid  = threadIdx.x;
    int bx   = blockIdx.x;
    int row0 = blockIdx.y * 128;
    int tx   = tid & 15;
    int ty   = tid >> 4;

    int a_r = tid >> 2;
    int a_c = (tid & 3) << 2;
    int b_r = tid >> 5;
    int b_c = (tid & 31) << 2;

    float acc[8][8];
    #pragma unroll
    for (int i = 0; i < 8; i++)
        #pragma unroll
        for (int j = 0; j < 8; j++) acc[i][j] = 0.0f;

    for (int k0 = 0; k0 < Kk; k0 += 16) {
        #pragma unroll
        for (int p = 0; p < 2; p++) {
            int r = row0 + a_r + p * 64;
            float4 v = (r < MR)
                ? *(const float4*)(A + (size_t)r * Kk + k0 + a_c)
                : make_float4(0.f, 0.f, 0.f, 0.f);
            As[a_c + 0][a_r + p * 64] = v.x;
            As[a_c + 1][a_r + p * 64] = v.y;
            As[a_c + 2][a_r + p * 64] = v.z;
            As[a_c + 3][a_r + p * 64] = v.w;
        }
        #pragma unroll
        for (int p = 0; p < 2; p++) {
            int kr = k0 + b_r + p * 8;
            *(float4*)(&Bs[b_r + p * 8][b_c]) =
                *(const float4*)(Bm + (size_t)kr * Nn + bx * 128 + b_c);
        }
        __syncthreads();

        #pragma unroll
        for (int k = 0; k < 16; k++) {
            float af[8], bf[8];
            *(float4*)(af)     = *(const float4*)(&As[k][ty * 4]);
            *(float4*)(af + 4) = *(const float4*)(&As[k][ty * 4 + 64]);
            *(float4*)(bf)     = *(const float4*)(&Bs[k][tx * 4]);
            *(float4*)(bf + 4) = *(const float4*)(&Bs[k][tx * 4 + 64]);
            #pragma unroll
            for (int i = 0; i < 8; i++)
                #pragma unroll
                for (int j = 0; j < 8; j++)
                    acc[i][j] = fmaf(af[i], bf[j], acc[i][j]);
        }
        __syncthreads();
    }

    #pragma unroll
    for (int i = 0; i < 8; i++) {
        int row = row0 + ty * 4 + ((i & 4) ? 64 : 0) + (i & 3);
        if (row >= MR) continue;
        float prow = policy[row];
        #pragma unroll
        for (int j = 0; j < 8; j++) {
            int col = bx * 128 + tx * 4 + ((j & 4) ? 64 : 0) + (j & 3);
            Cout[(size_t)row * Nn + col] = acc[i][j] * prow;
        }
    }
}

// ---------------------------------------------------------------- TF32 tensor-core GEMM — R10 verbatim
template <int MODE>
__global__ __launch_bounds__(256, 2)
void tf32_gemm(const float* __restrict__ Bm,
               const float* __restrict__ bias,
               const float* __restrict__ aux,
               float* __restrict__ Cext)
{
    constexpr int Nn = (MODE == 2) ? C4 : CC;
    constexpr int Kk = (MODE == 3) ? C4 : CC;
    const float* A = (MODE == 1) ? g_xo : (MODE == 2) ? g_ln2 : g_fc1;
    float* Cout    = (MODE == 1) ? g_x2 : (MODE == 2) ? g_fc1 : Cext;

    __shared__ uint32_t As[128][36];   // [m][k], conflict-free
    __shared__ uint32_t Bs[32][136];   // [k][n], conflict-free

    int tid  = threadIdx.x;
    int lane = tid & 31;
    int wid  = tid >> 5;
    int bx   = blockIdx.x;
    int row0 = blockIdx.y * 128;

    int wm = (wid & 1) * 64;
    int wn = (wid >> 1) * 32;
    int fr = lane >> 2;
    int fc = lane & 3;

    float acc[4][4][4];
    #pragma unroll
    for (int i = 0; i < 4; i++)
        #pragma unroll
        for (int j = 0; j < 4; j++)
            #pragma unroll
            for (int q = 0; q < 4; q++) acc[i][j][q] = 0.0f;

    for (int k0 = 0; k0 < Kk; k0 += 32) {
        #pragma unroll
        for (int p = 0; p < 4; p++) {
            int idx = tid + p * 256;
            int r   = idx >> 3;
            int c   = (idx & 7) << 2;
            int gr  = row0 + r;
            float4 v = (gr < MR)
                ? *(const float4*)(A + (size_t)gr * Kk + k0 + c)
                : make_float4(0.f, 0.f, 0.f, 0.f);
            As[r][c + 0] = f2tf32(v.x);
            As[r][c + 1] = f2tf32(v.y);
            As[r][c + 2] = f2tf32(v.z);
            As[r][c + 3] = f2tf32(v.w);
        }
        #pragma unroll
        for (int p = 0; p < 4; p++) {
            int idx = tid + p * 256;
            int kr  = idx >> 5;
            int c   = (idx & 31) << 2;
            float4 v = *(const float4*)(Bm + (size_t)(k0 + kr) * Nn + bx * 128 + c);
            Bs[kr][c + 0] = f2tf32(v.x);
            Bs[kr][c + 1] = f2tf32(v.y);
            Bs[kr][c + 2] = f2tf32(v.z);
            Bs[kr][c + 3] = f2tf32(v.w);
        }
        __syncthreads();

        #pragma unroll
        for (int sub = 0; sub < 4; sub++) {
            int kb = sub * 8;
            uint32_t a[4][4], b[4][2];
            #pragma unroll
            for (int i = 0; i < 4; i++) {
                int mr = wm + i * 16 + fr;
                a[i][0] = As[mr    ][kb + fc    ];
                a[i][1] = As[mr + 8][kb + fc    ];
                a[i][2] = As[mr    ][kb + fc + 4];
                a[i][3] = As[mr + 8][kb + fc + 4];
            }
            #pragma unroll
            for (int j = 0; j < 4; j++) {
                int nc = wn + j * 8 + fr;
                b[j][0] = Bs[kb + fc    ][nc];
                b[j][1] = Bs[kb + fc + 4][nc];
            }
            #pragma unroll
            for (int i = 0; i < 4; i++)
                #pragma unroll
                for (int j = 0; j < 4; j++)
                    asm volatile(
                        "mma.sync.aligned.m16n8k8.row.col.f32.tf32.tf32.f32 "
                        "{%0,%1,%2,%3}, {%4,%5,%6,%7}, {%8,%9}, {%0,%1,%2,%3};"
                        : "+f"(acc[i][j][0]), "+f"(acc[i][j][1]),
                          "+f"(acc[i][j][2]), "+f"(acc[i][j][3])
                        : "r"(a[i][0]), "r"(a[i][1]), "r"(a[i][2]), "r"(a[i][3]),
                          "r"(b[j][0]), "r"(b[j][1]));
        }
        __syncthreads();
    }

    #pragma unroll
    for (int i = 0; i < 4; i++) {
        #pragma unroll
        for (int half = 0; half < 2; half++) {
            int row = row0 + wm + i * 16 + fr + half * 8;
            if (row >= MR) continue;
            float prow = 0.f;
            int   rmap = 0, bidx = 0;
            if (MODE == 1) { prow = g_pol[row]; rmap = g_rowmap[row]; bidx = row / NN; }
            if (MODE == 3) prow = g_pol[row];
            #pragma unroll
            for (int j = 0; j < 4; j++) {
                #pragma unroll
                for (int q = 0; q < 2; q++) {
                    int col = bx * 128 + wn + j * 8 + 2 * fc + q;
                    float a = acc[i][j][half * 2 + q];
                    size_t oidx = (size_t)row * Nn + col;
                    if (MODE == 1) {
                        float xg = (rmap >= 0)
                            ? aux[(size_t)(bidx * NN + rmap) * CC + col] : 0.0f;
                        Cout[oidx] = xg + (a + bias[col]) * prow;
                    } else if (MODE == 2) {
                        float tv = a + bias[col];
                        Cout[oidx] = tv * 0.5f * (1.0f + erff(tv * 0.70710678118654752f));
                    } else {
                        Cout[oidx] = (g_x2[oidx] + a + bias[col]) * prow;
                    }
                }
            }
        }
    }
}

// ---------------------------------------------------------------- fused QK^T + softmax — R15 verbatim
#define QKS_SMEM ((2*64*68 + 64*200) * 4)   /* 84 KB dynamic */

__global__ __launch_bounds__(256)
void qks_kernel(const float* __restrict__ policy)
{
    extern __shared__ float sm[];
    float* Qs = sm;               // [64][68]  (k-major: Qs[k][r])
    float* Ks = sm + 64 * 68;     // [64][68]
    float* S  = sm + 2 * 64 * 68; // [64][200] score rows

    int bh = blockIdx.x;
    int b  = bh / HH, h = bh - b * HH;
    int n0 = blockIdx.y * 64;
    int t  = threadIdx.x;
    int tx = t & 15, ty = t >> 4;

    for (int e = t; e < 4096; e += 256) {
        int r = e >> 6, k = e & 63;
        int n = n0 + r;
        Qs[k * 68 + r] = (n < NN) ? g_qkv[(size_t)(b * NN + n) * C3 + h * HD + k] : 0.f;
    }

    for (int m0 = 0; m0 < NN; m0 += 64) {
        if (m0) __syncthreads();
        for (int e = t; e < 4096; e += 256) {
            int r = e >> 6, k = e & 63;
            int m = m0 + r;
            Ks[k * 68 + r] = (m < NN) ? g_qkv[(size_t)(b * NN + m) * C3 + CC + h * HD + k] : 0.f;
        }
        __syncthreads();

        float acc[4][4];
        #pragma unroll
        for (int i = 0; i < 4; i++)
            #pragma unroll
            for (int j = 0; j < 4; j++) acc[i][j] = 0.f;

        #pragma unroll 8
        for (int k = 0; k < 64; k++) {
            float4 qa = *(const float4*)(&Qs[k * 68 + ty * 4]);
            float4 ka = *(const float4*)(&Ks[k * 68 + tx * 4]);
            float q[4]  = {qa.x, qa.y, qa.z, qa.w};
            float kv[4] = {ka.x, ka.y, ka.z, ka.w};
            #pragma unroll
            for (int i = 0; i < 4; i++)
                #pragma unroll
                for (int j = 0; j < 4; j++)
                    acc[i][j] = fmaf(q[i], kv[j], acc[i][j]);
        }

        #pragma unroll
        for (int i = 0; i < 4; i++)
            #pragma unroll
            for (int j = 0; j < 4; j++) {
                int col = m0 + tx * 4 + j;
                if (col < 200)
                    S[(ty * 4 + i) * 200 + col] = acc[i][j] * 0.125f;
            }
    }
    __syncthreads();

    int w = t >> 5, lane = t & 31;
    for (int r = w; r < 64; r += 8) {
        int n = n0 + r;
        if (n >= NN) break;
        const float* row = &S[r * 200];

        float v[7];
        float mx = -1e30f;
        #pragma unroll
        for (int i = 0; i < 7; i++) {
            int m = lane + i * 32;
            v[i] = (m < NN) ? row[m] : -1e30f;
            mx = fmaxf(mx, v[i]);
        }
        #pragma unroll
        for (int o = 16; o > 0; o >>= 1) mx = fmaxf(mx, __shfl_xor_sync(0xffffffffu, mx, o));

        float s = 0.f;
        #pragma unroll
        for (int i = 0; i < 7; i++) {
            int m = lane + i * 32;
            if (m < NN) {
                float p = (m == n) ? 1.0f : policy[b * NN + m];
                v[i] = expf(v[i] - mx) * p;
                s += v[i];
            }
        }
        #pragma unroll
        for (int o = 16; o > 0; o >>= 1) s += __shfl_xor_sync(0xffffffffu, s, o);

        float inv = 1.0f / (s + 1e-6f);
        const float c = (float)(1e-6 / 197.0);
        float* orow = g_attn + ((size_t)bh * NN + n) * NN;
        #pragma unroll
        for (int i = 0; i < 7; i++) {
            int m = lane + i * 32;
            if (m < NN) orow[m] = (v[i] + c) * inv;
        }
    }
}

// ---------------------------------------------------------------- ATS sampling v2 (fp64, parallelized)
// Same math as v1, but: block-parallel fp64 max/sum reductions, parallel
// Hillis-Steele cumsum, parallel min/max, ILP-unrolled dot products.
// Only effect on values: fp64 reassociation (~1e-16) — five orders below the
// fp64-vs-fp32-reference deviation (~1e-7) the passing picks already tolerate.

__device__ __forceinline__ double blk_max_d(double v, double* red, int t) {
    #pragma unroll
    for (int o = 16; o > 0; o >>= 1) v = fmax(v, __shfl_xor_sync(0xffffffffu, v, o));
    if ((t & 31) == 0) red[t >> 5] = v;
    __syncthreads();
    if (t < 32) {
        double r = (t < 8) ? red[t] : -1e300;
        #pragma unroll
        for (int o = 4; o > 0; o >>= 1) r = fmax(r, __shfl_xor_sync(0xffffffffu, r, o));
        if (t == 0) red[0] = r;
    }
    __syncthreads();
    double out = red[0];
    __syncthreads();
    return out;
}
__device__ __forceinline__ double blk_min_d(double v, double* red, int t) {
    #pragma unroll
    for (int o = 16; o > 0; o >>= 1) v = fmin(v, __shfl_xor_sync(0xffffffffu, v, o));
    if ((t & 31) == 0) red[t >> 5] = v;
    __syncthreads();
    if (t < 32) {
        double r = (t < 8) ? red[t] : 1e300;
        #pragma unroll
        for (int o = 4; o > 0; o >>= 1) r = fmin(r, __shfl_xor_sync(0xffffffffu, r, o));
        if (t == 0) red[0] = r;
    }
    __syncthreads();
    double out = red[0];
    __syncthreads();
    return out;
}
__device__ __forceinline__ double blk_sum_d(double v, double* red, int t) {
    #pragma unroll
    for (int o = 16; o > 0; o >>= 1) v += __shfl_xor_sync(0xffffffffu, v, o);
    if ((t & 31) == 0) red[t >> 5] = v;
    __syncthreads();
    if (t < 32) {
        double r = (t < 8) ? red[t] : 0.0;
        #pragma unroll
        for (int o = 4; o > 0; o >>= 1) r += __shfl_xor_sync(0xffffffffu, r, o);
        if (t == 0) red[0] = r;
    }
    __syncthreads();
    double out = red[0];
    __syncthreads();
    return out;
}

__global__ void sample_kernel(const float* __restrict__ policy)
{
    int b = blockIdx.x;
    int t = threadIdx.x;

    __shared__ double draw[NN];
    __shared__ double scacc[NN];
    __shared__ double scn[196], cdfs[196], ncdf[196];
    __shared__ int    ord[196], pick[196], spick[196], uu[196], uq[196];
    __shared__ double red8[8];

    if (t < NN) scacc[t] = 0.0;
    __syncthreads();

    // smoothed CLS-row attention accumulated over heads
    for (int h = 0; h < HH; h++) {
        if (t < NN) {
            const float* q0 = &g_qkv[(size_t)(b * NN) * C3 + h * HD];
            const float* km = &g_qkv[(size_t)(b * NN + t) * C3 + CC + h * HD];
            double s0 = 0.0, s1 = 0.0, s2 = 0.0, s3 = 0.0;
            #pragma unroll
            for (int d = 0; d < HD; d += 4) {
                s0 += (double)q0[d    ] * (double)km[d    ];
                s1 += (double)q0[d + 1] * (double)km[d + 1];
                s2 += (double)q0[d + 2] * (double)km[d + 2];
                s3 += (double)q0[d + 3] * (double)km[d + 3];
            }
            draw[t] = ((s0 + s1) + (s2 + s3)) * 0.125;
        }
        __syncthreads();

        double mx = blk_max_d((t < NN) ? draw[t] : -1e300, red8, t);

        double val = 0.0;
        if (t < NN) {
            double p = (t == 0) ? 1.0 : (double)policy[b * NN + t];
            val = exp(draw[t] - mx) * p;
        }
        double den = blk_sum_d(val, red8, t) + 1e-6;

        const double c = 1e-6 / 197.0;
        if (t < NN) scacc[t] += (val + c) / den;
        __syncthreads();
    }

    // score[j] = attn_cls_sum[j+1] * ||v[j+1]||, 8-way ILP dot
    if (t < 196) {
        int m = t + 1;
        const float* v = &g_qkv[(size_t)(b * NN + m) * C3 + 2 * CC];
        double p0 = 0, p1 = 0, p2 = 0, p3 = 0, p4 = 0, p5 = 0, p6 = 0, p7 = 0;
        for (int d = 0; d < CC; d += 8) {
            double x0 = v[d], x1 = v[d+1], x2 = v[d+2], x3 = v[d+3];
            double x4 = v[d+4], x5 = v[d+5], x6 = v[d+6], x7 = v[d+7];
            p0 += x0*x0; p1 += x1*x1; p2 += x2*x2; p3 += x3*x3;
            p4 += x4*x4; p5 += x5*x5; p6 += x6*x6; p7 += x7*x7;
        }
        double s = ((p0+p1)+(p2+p3)) + ((p4+p5)+(p6+p7));
        scn[t] = scacc[m] * sqrt(s);
    }
    __syncthreads();

    double ssum = blk_sum_d((t < 196) ? scn[t] : 0.0, red8, t);
    if (t < 196) scn[t] = scn[t] / ssum;
    __syncthreads();

    // stable ascending argsort via rank counting
    if (t < 196) {
        double sj = scn[t];
        int r = 0;
        for (int i = 0; i < 196; i++) {
            double si = scn[i];
            if (si < sj || (si == sj && i < t)) r++;
        }
        ord[r] = t;
    }
    __syncthreads();

    // parallel inclusive scan (Hillis-Steele) for cdf
    if (t < 196) cdfs[t] = scn[ord[t]];
    __syncthreads();
    for (int off = 1; off < 196; off <<= 1) {
        double add = 0.0;
        if (t < 196 && t >= off) add = cdfs[t - off];
        __syncthreads();
        if (t < 196 && t >= off) cdfs[t] += add;
        __syncthreads();
    }

    double mn  = blk_min_d((t < 196) ? cdfs[t] :  1e300, red8, t);
    double mx2 = blk_max_d((t < 196) ? cdfs[t] : -1e300, red8, t);
    double rng = mx2 - mn;
    if (t < 196) ncdf[t] = (cdfs[t] - mn) / rng;
    __syncthreads();

    double ysv = 1e300;
    if (t < 196) ysv = ncdf[t] + ((ncdf[t] == 0.0) ? 1e8 : 0.0);
    double ys_start = blk_min_d(ysv, red8, t);

    // inverse transform sampling: first-occurrence argmin
    if (t < 196) {
        double lin = (t == 195) ? 1.0 : ((double)t * (1.0 / 195.0));
        double ys  = ys_start + (lin * 195.0 - ys_start * (double)t) / 195.0;
        double best = 1e30;
        int arg = 0;
        for (int j = 0; j < 196; j++) {
            double d2 = fabs(ys - ncdf[j]);
            if (d2 < best) { best = d2; arg = j; }
        }
        pick[t] = arg;
    }
    __syncthreads();

    // sort picks ascending (stable ranks)
    if (t < 196) {
        int pj = pick[t];
        int r = 0;
        for (int i = 0; i < 196; i++) {
            int pi = pick[i];
            if (pi < pj || (pi == pj && i < t)) r++;
        }
        spick[r] = pj;
    }
    __syncthreads();
    // kill duplicates -> max_value (=196), literal shift-left rule
    if (t < 196) {
        int sl = (t < 195) ? spick[t + 1] : 1;
        uu[t] = (sl - spick[t] == 0) ? 196 : spick[t];
    }
    __syncthreads();
    // final sort
    if (t < 196) {
        int vj = uu[t];
        int r = 0;
        for (int i = 0; i < 196; i++) {
            int vi = uu[i];
            if (vi < vj || (vi == vj && i < t)) r++;
        }
        uq[r] = vj;
    }
    __syncthreads();

    if (t == 0) { g_rowmap[b * NN] = 0; g_pol[b * NN] = 1.0f; }
    if (t < 196) {
        int u = uq[t];
        g_pol[b * NN + 1 + t]    = (u != 196) ? 1.0f : 0.0f;
        g_rowmap[b * NN + 1 + t] = (u < 196) ? (1 + ord[u]) : -1;
    }
}

// ---------------------------------------------------------------- gathered attn @ V — R15 verbatim
__global__ __launch_bounds__(256)
void av_kernel()
{
    int bh = blockIdx.x;
    int b  = bh / HH, h = bh - b * HH;
    int n0 = blockIdx.y * 64;

    __shared__ float As[64][68];
    __shared__ float Vs[64][68];
    __shared__ int   rm[64];

    int t = threadIdx.x;
    if (t < 64) {
        int n = n0 + t;
        rm[t] = (n < NN) ? g_rowmap[b * NN + n] : -1;
    }
    __syncthreads();

    int tx = t & 15, ty = t >> 4;
    float acc[4][4];
    #pragma unroll
    for (int i = 0; i < 4; i++)
        #pragma unroll
        for (int j = 0; j < 4; j++) acc[i][j] = 0.f;

    for (int m0 = 0; m0 < NN; m0 += 64) {
        for (int e = t; e < 4096; e += 256) {
            int i = e >> 6, kk = e & 63;
            int r = rm[i];
            int m = m0 + kk;
            As[kk][i] = (r >= 0 && m < NN)
                ? g_attn[((size_t)bh * NN + r) * NN + m] : 0.f;
        }
        for (int e = t; e < 4096; e += 256) {
            int kk = e >> 6, d = e & 63;
            int m = m0 + kk;
            Vs[kk][d] = (m < NN)
                ? g_qkv[(size_t)(b * NN + m) * C3 + 2 * CC + h * HD + d] : 0.f;
        }
        __syncthreads();

        #pragma unroll 8
        for (int kk = 0; kk < 64; kk++) {
            float4 aa4 = *(const float4*)(&As[kk][ty * 4]);
            float4 vv4 = *(const float4*)(&Vs[kk][tx * 4]);
            float aa[4] = {aa4.x, aa4.y, aa4.z, aa4.w};
            float vv[4] = {vv4.x, vv4.y, vv4.z, vv4.w};
            #pragma unroll
            for (int i = 0; i < 4; i++)
                #pragma unroll
                for (int j = 0; j < 4; j++)
                    acc[i][j] = fmaf(aa[i], vv[j], acc[i][j]);
        }
        __syncthreads();
    }

    #pragma unroll
    for (int i = 0; i < 4; i++) {
        int n = n0 + ty * 4 + i;
        if (n >= NN) continue;
        #pragma unroll
        for (int j = 0; j < 4; j++)
            g_xo[(size_t)(b * NN + n) * CC + h * HD + tx * 4 + j] = acc[i][j];
    }
}

// ---------------------------------------------------------------- launch
extern "C" void kernel_launch(void* const* d_in, const int* in_sizes, int n_in,
                              void* d_out, int out_size)
{
    const float* x      = (const float*)d_in[0];
    const float* policy = (const float*)d_in[1];
    const float* w_qkv  = (const float*)d_in[2];
    const float* w_proj = (const float*)d_in[3];
    const float* b_proj = (const float*)d_in[4];
    const float* g1     = (const float*)d_in[5];
    const float* b1     = (const float*)d_in[6];
    const float* g2     = (const float*)d_in[7];
    const float* b2     = (const float*)d_in[8];
    const float* w_fc1  = (const float*)d_in[9];
    const float* b_fc1  = (const float*)d_in[10];
    const float* w_fc2  = (const float*)d_in[11];
    const float* b_fc2  = (const float*)d_in[12];
    float* out = (float*)d_out;

    cudaFuncSetAttribute(qks_kernel, cudaFuncAttributeMaxDynamicSharedMemorySize, QKS_SMEM);

    const int MTILES = (MR + 127) / 128;   // 99

    // 1. LN1
    ln_kernel<<<MR, 256>>>(x, g1, b1, 0);
    // 2. QKV GEMM: fp32 (feeds the discrete sampling path)
    sgemm_qkv<<<dim3(C3 / 128, MTILES), 256>>>(w_qkv, policy);
    // 3. fused Q K^T * scale + softmax-with-policy -> g_attn
    qks_kernel<<<dim3(BH, 4), 256, QKS_SMEM>>>(policy);
    // 4. ATS sampling v2 (fp64, parallel reductions) -> rowmap / pol
    sample_kernel<<<BB, 256>>>(policy);
    // 5. gathered attn @ V
    av_kernel<<<dim3(BH, 4), 256>>>();
    // 6. proj GEMM (TF32 TC) + bias, *pol, + gathered x residual -> x2
    tf32_gemm<1><<<dim3(CC / 128, MTILES), 256>>>(w_proj, b_proj, x, nullptr);
    // 7. LN2
    ln_kernel<<<MR, 256>>>(nullptr, g2, b2, 1);
    // 8. FC1 GEMM (TF32 TC) + exact GELU
    tf32_gemm<2><<<dim3(C4 / 128, MTILES), 256>>>(w_fc1, b_fc1, nullptr, nullptr);
    // 9. FC2 GEMM (TF32 TC) + residual + *pol -> out
    tf32_gemm<3><<<dim3(CC / 128, MTILES), 256>>>(w_fc2, b_fc2, nullptr, out);
}